// round 4
// baseline (speedup 1.0000x reference)
#include <cuda_runtime.h>
#include <cuda_bf16.h>

#define NN 20000
#define EE 320000
#define HH 8
#define DD 32
#define F1 128
#define HD 256   // H*D
#define TR 72    // gemm row tile (8 rowgroups x 9 rows)

// ---------------- scratch (device globals; no allocation allowed) -------------
__device__ float g_feat[NN * HD];      // [N, dim*8+head] transposed features
__device__ float g_el[NN * HH];
__device__ float g_er[NN * HH];
__device__ float g_h[NN * DD];         // layer-1 output
__device__ float g_Wp1[F1 * HD];       // column-permuted weights, layer 1
__device__ float g_Wp2[DD * HD];       // column-permuted weights, layer 2
__device__ float g_alp1[HD], g_arp1[HD];
__device__ float g_alp2[HD], g_arp2[HD];
__device__ int   g_cnt[NN];            // INVARIANT: zero on entry to every call
__device__ int   g_rowptr[NN + 1];
__device__ int   g_fill[NN];
__device__ int   g_esrc[EE];           // src node per CSR slot

// ---------------- hist + weight permutation (merged, independent work) --------
// blocks [0,1250): histogram of dst
// blocks [1250,1378): perm W1   block 1378: alp1/arp1
// blocks [1379,1411): perm W2   block 1411: alp2/arp2
__global__ void hist_perm_kernel(const int* __restrict__ dst,
                                 const float* __restrict__ W1,
                                 const float* __restrict__ al1,
                                 const float* __restrict__ ar1,
                                 const float* __restrict__ W2,
                                 const float* __restrict__ al2,
                                 const float* __restrict__ ar2) {
    int b = blockIdx.x;
    int tid = threadIdx.x;
    if (b < 1250) {
        int e = b * 256 + tid;
        if (e < EE) atomicAdd(&g_cnt[dst[e]], 1);
    } else if (b < 1378) {
        int t = (b - 1250) * 256 + tid;      // < F1*HD = 32768
        int k = t >> 8, j = t & 255;
        int L = ((j & 7) << 5) | (j >> 3);
        g_Wp1[t] = W1[k * HD + L];
    } else if (b == 1378) {
        int L = ((tid & 7) << 5) | (tid >> 3);
        g_alp1[tid] = al1[L];
        g_arp1[tid] = ar1[L];
    } else if (b < 1411) {
        int t = (b - 1379) * 256 + tid;      // < DD*HD = 8192
        int k = t >> 8, j = t & 255;
        int L = ((j & 7) << 5) | (j >> 3);
        g_Wp2[t] = W2[k * HD + L];
    } else {
        int L = ((tid & 7) << 5) | (tid >> 3);
        g_alp2[tid] = al2[L];
        g_arp2[tid] = ar2[L];
    }
}

// ---------------- scan: exclusive prefix over g_cnt; re-zeroes g_cnt ----------
__global__ void scan_kernel() {
    __shared__ int ssum[1024];
    int t = threadIdx.x;
    const int chunk = (NN + 1023) / 1024;  // 20
    int b = t * chunk;
    int e = min(b + chunk, NN);
    int s = 0;
    for (int i = b; i < e; i++) s += g_cnt[i];
    ssum[t] = s;
    __syncthreads();
    for (int off = 1; off < 1024; off <<= 1) {
        int v = (t >= off) ? ssum[t - off] : 0;
        __syncthreads();
        ssum[t] += v;
        __syncthreads();
    }
    int pref = (t > 0) ? ssum[t - 1] : 0;
    for (int i = b; i < e; i++) {
        int c = g_cnt[i];
        g_rowptr[i] = pref;
        g_fill[i]   = pref;
        g_cnt[i]    = 0;               // restore invariant for next replay
        pref += c;
    }
    if (t == 1023) g_rowptr[NN] = ssum[1023];
}

// ---------------- GEMM: register-tiled, K-chunked smem, optional scatter ------
// feat[row][j] = sum_k X[row][k] * Wp[k][j].
// 512 threads, tile 72 rows x 256 cols; thread: 4 cols x 9 rows.
// W staged through smem in 64-row chunks -> ~100KB smem -> 2 blocks/SM.
template <int K, bool SCAT>
__global__ __launch_bounds__(512) void gemm_kernel(const float* __restrict__ X,
                                                   const float* __restrict__ Wp,
                                                   float* __restrict__ feat,
                                                   int n,
                                                   const int* __restrict__ src,
                                                   const int* __restrict__ dst) {
    constexpr int KC = (K > 64) ? 64 : K;
    extern __shared__ float sh[];
    float* Wsh = sh;            // [KC][256] k-major
    float* Xsh = sh + KC * HD;  // [TR][K]
    int tid = threadIdx.x;

    if (SCAT) {  // CSR scatter folded in (scan completed in previous launch)
        for (int e = blockIdx.x * 512 + tid; e < EE; e += gridDim.x * 512) {
            int p = atomicAdd(&g_fill[dst[e]], 1);
            g_esrc[p] = src[e];
        }
    }

    int r0 = blockIdx.x * TR;
    int nr = min(TR, n - r0);
    for (int idx = tid; idx < nr * K; idx += 512)
        Xsh[idx] = X[(size_t)r0 * K + idx];

    int col = (tid & 63) * 4;
    int rg = (tid >> 6) * 9;

    float acc[9][4];
#pragma unroll
    for (int r = 0; r < 9; r++)
#pragma unroll
        for (int c = 0; c < 4; c++) acc[r][c] = 0.f;

    for (int kc = 0; kc < K; kc += KC) {
        __syncthreads();
        for (int idx = tid; idx < KC * HD; idx += 512)
            Wsh[idx] = Wp[kc * HD + idx];
        __syncthreads();

#pragma unroll 4
        for (int k = 0; k < KC; k += 4) {
            float4 w0 = *(const float4*)(Wsh + (k + 0) * HD + col);
            float4 w1 = *(const float4*)(Wsh + (k + 1) * HD + col);
            float4 w2 = *(const float4*)(Wsh + (k + 2) * HD + col);
            float4 w3 = *(const float4*)(Wsh + (k + 3) * HD + col);
#pragma unroll
            for (int r = 0; r < 9; r++) {
                float4 xv = *(const float4*)(Xsh + (rg + r) * K + kc + k);
                acc[r][0] = fmaf(xv.x, w0.x, acc[r][0]);
                acc[r][1] = fmaf(xv.x, w0.y, acc[r][1]);
                acc[r][2] = fmaf(xv.x, w0.z, acc[r][2]);
                acc[r][3] = fmaf(xv.x, w0.w, acc[r][3]);
                acc[r][0] = fmaf(xv.y, w1.x, acc[r][0]);
                acc[r][1] = fmaf(xv.y, w1.y, acc[r][1]);
                acc[r][2] = fmaf(xv.y, w1.z, acc[r][2]);
                acc[r][3] = fmaf(xv.y, w1.w, acc[r][3]);
                acc[r][0] = fmaf(xv.z, w2.x, acc[r][0]);
                acc[r][1] = fmaf(xv.z, w2.y, acc[r][1]);
                acc[r][2] = fmaf(xv.z, w2.z, acc[r][2]);
                acc[r][3] = fmaf(xv.z, w2.w, acc[r][3]);
                acc[r][0] = fmaf(xv.w, w3.x, acc[r][0]);
                acc[r][1] = fmaf(xv.w, w3.y, acc[r][1]);
                acc[r][2] = fmaf(xv.w, w3.z, acc[r][2]);
                acc[r][3] = fmaf(xv.w, w3.w, acc[r][3]);
            }
        }
    }

#pragma unroll
    for (int r = 0; r < 9; r++) {
        int row = rg + r;
        if (row < nr) {
            float4 v = make_float4(acc[r][0], acc[r][1], acc[r][2], acc[r][3]);
            *(float4*)(feat + (size_t)(r0 + row) * HD + col) = v;
        }
    }
}

// ---------------- attention logits (warp per node) ----------------------------
__global__ void elr_kernel(const float* __restrict__ alp,
                           const float* __restrict__ arp, int n) {
    int gid = blockIdx.x * blockDim.x + threadIdx.x;
    int node = gid >> 5;
    if (node >= n) return;
    int lane = gid & 31;
    const float4* fp = (const float4*)(g_feat + (size_t)node * HD + lane * 8);
    float4 f0 = fp[0], f1 = fp[1];
    const float4* ap = (const float4*)(alp + lane * 8);
    float4 a0 = ap[0], a1 = ap[1];
    const float4* bp = (const float4*)(arp + lane * 8);
    float4 b0 = bp[0], b1 = bp[1];
    float pa[8] = {f0.x * a0.x, f0.y * a0.y, f0.z * a0.z, f0.w * a0.w,
                   f1.x * a1.x, f1.y * a1.y, f1.z * a1.z, f1.w * a1.w};
    float pb[8] = {f0.x * b0.x, f0.y * b0.y, f0.z * b0.z, f0.w * b0.w,
                   f1.x * b1.x, f1.y * b1.y, f1.z * b1.z, f1.w * b1.w};
#pragma unroll
    for (int h = 0; h < 8; h++) {
#pragma unroll
        for (int off = 16; off; off >>= 1) {
            pa[h] += __shfl_xor_sync(0xffffffffu, pa[h], off);
            pb[h] += __shfl_xor_sync(0xffffffffu, pb[h], off);
        }
    }
    if (lane == 0) {
        float* elp = g_el + node * HH;
        float* erp = g_er + node * HH;
        elp[0] = pa[0]; elp[1] = pa[1]; elp[2] = pa[2]; elp[3] = pa[3];
        elp[4] = pa[4]; elp[5] = pa[5]; elp[6] = pa[6]; elp[7] = pa[7];
        erp[0] = pb[0]; erp[1] = pb[1]; erp[2] = pb[2]; erp[3] = pb[3];
        erp[4] = pb[4]; erp[5] = pb[5]; erp[6] = pb[6]; erp[7] = pb[7];
    }
}

// ---------------- aggregation (warp per dst node, fused softmax) --------------
template <bool RELU_BEFORE_MEAN>
__global__ void agg_kernel(const float* __restrict__ bias,
                           float* __restrict__ out) {
    int node = blockIdx.x * (blockDim.x >> 5) + (threadIdx.x >> 5);
    if (node >= NN) return;
    int lane = threadIdx.x & 31;
    int hh = lane & 7;
    float er_l = g_er[node * HH + hh];
    int beg = g_rowptr[node], end = g_rowptr[node + 1];

    float acc[8];
#pragma unroll
    for (int h = 0; h < 8; h++) acc[h] = 0.f;
    float den_l = 0.f;

    int i = beg;
    for (; i + 2 <= end; i += 2) {
        int s0 = g_esrc[i];
        int s1 = g_esrc[i + 1];
        float el0 = __ldg(g_el + s0 * HH + hh);
        float el1 = __ldg(g_el + s1 * HH + hh);
        const float4* fp0 = (const float4*)(g_feat + (size_t)s0 * HD + lane * 8);
        const float4* fp1 = (const float4*)(g_feat + (size_t)s1 * HD + lane * 8);
        float4 a0 = fp0[0], a1 = fp0[1];
        float4 c0 = fp1[0], c1 = fp1[1];
        float v0 = el0 + er_l; v0 = v0 > 0.f ? v0 : 0.2f * v0;
        float v1 = el1 + er_l; v1 = v1 > 0.f ? v1 : 0.2f * v1;
        float e0 = __expf(v0);
        float e1 = __expf(v1);
        den_l += e0 + e1;
#pragma unroll
        for (int h = 0; h < 8; h++) {
            float w0 = __shfl_sync(0xffffffffu, e0, h);
            float w1 = __shfl_sync(0xffffffffu, e1, h);
            float f0 = (h < 4) ? (&a0.x)[h] : (&a1.x)[h - 4];
            float f1 = (h < 4) ? (&c0.x)[h] : (&c1.x)[h - 4];
            acc[h] = fmaf(w0, f0, acc[h]);
            acc[h] = fmaf(w1, f1, acc[h]);
        }
    }
    if (i < end) {
        int s = g_esrc[i];
        float elv = __ldg(g_el + s * HH + hh);
        const float4* fp = (const float4*)(g_feat + (size_t)s * HD + lane * 8);
        float4 a0 = fp[0], a1 = fp[1];
        float v = elv + er_l; v = v > 0.f ? v : 0.2f * v;
        float e = __expf(v);
        den_l += e;
#pragma unroll
        for (int h = 0; h < 8; h++) {
            float w = __shfl_sync(0xffffffffu, e, h);
            float f = (h < 4) ? (&a0.x)[h] : (&a1.x)[h - 4];
            acc[h] = fmaf(w, f, acc[h]);
        }
    }

    float sum = 0.f;
#pragma unroll
    for (int h = 0; h < 8; h++) {
        float dh = __shfl_sync(0xffffffffu, den_l, h);
        float r = (dh > 0.f) ? acc[h] / dh : 0.f;
        r += bias[h * DD + lane];
        if (RELU_BEFORE_MEAN) r = fmaxf(r, 0.f);
        sum += r;
    }
    out[node * DD + lane] = sum * 0.125f;
}

// ---------------- launcher -----------------------------------------------------
extern "C" void kernel_launch(void* const* d_in, const int* in_sizes, int n_in,
                              void* d_out, int out_size) {
    const float* x   = (const float*)d_in[0];
    const int*   src = (const int*)d_in[1];
    const int*   dst = (const int*)d_in[2];
    const float* W1  = (const float*)d_in[3];
    const float* al1 = (const float*)d_in[4];
    const float* ar1 = (const float*)d_in[5];
    const float* b1  = (const float*)d_in[6];
    const float* W2  = (const float*)d_in[7];
    const float* al2 = (const float*)d_in[8];
    const float* ar2 = (const float*)d_in[9];
    const float* b2  = (const float*)d_in[10];
    float* out = (float*)d_out;

    float *feat, *hbuf, *Wp1, *Wp2, *alp1, *arp1, *alp2, *arp2;
    cudaGetSymbolAddress((void**)&feat, g_feat);
    cudaGetSymbolAddress((void**)&hbuf, g_h);
    cudaGetSymbolAddress((void**)&Wp1, g_Wp1);
    cudaGetSymbolAddress((void**)&Wp2, g_Wp2);
    cudaGetSymbolAddress((void**)&alp1, g_alp1);
    cudaGetSymbolAddress((void**)&arp1, g_arp1);
    cudaGetSymbolAddress((void**)&alp2, g_alp2);
    cudaGetSymbolAddress((void**)&arp2, g_arp2);

    const int NT = (NN + TR - 1) / TR;  // 278 tiles

    constexpr int smem1 = (64 * HD + TR * F1) * sizeof(float);  // 102400
    constexpr int smem2 = (DD * HD + TR * DD) * sizeof(float);  // 41984
    cudaFuncSetAttribute(gemm_kernel<F1, true>,
                         cudaFuncAttributeMaxDynamicSharedMemorySize, smem1);
    cudaFuncSetAttribute(gemm_kernel<DD, false>,
                         cudaFuncAttributeMaxDynamicSharedMemorySize, smem2);

    // 1: histogram + both weight permutations (independent work, one launch)
    hist_perm_kernel<<<1412, 256>>>(dst, W1, al1, ar1, W2, al2, ar2);
    // 2: prefix scan (also restores g_cnt = 0 invariant)
    scan_kernel<<<1, 1024>>>();
    // 3: layer-1 GEMM with CSR scatter folded into its prologue
    gemm_kernel<F1, true><<<NT, 512, smem1>>>(x, Wp1, feat, NN, src, dst);
    // 4-5: layer-1 logits + aggregation
    elr_kernel<<<(NN * 32 + 255) / 256, 256>>>(alp1, arp1, NN);
    agg_kernel<true><<<(NN + 7) / 8, 256>>>(b1, hbuf);
    // 6-8: layer 2
    gemm_kernel<DD, false><<<NT, 512, smem2>>>(hbuf, Wp2, feat, NN, src, dst);
    elr_kernel<<<(NN * 32 + 255) / 256, 256>>>(alp2, arp2, NN);
    agg_kernel<false><<<(NN + 7) / 8, 256>>>(b2, out);
}

// round 5
// speedup vs baseline: 1.3190x; 1.3190x over previous
#include <cuda_runtime.h>
#include <cuda_fp16.h>
#include <cuda_bf16.h>

#define NN 20000
#define EE 320000
#define HH 8
#define DD 32
#define F1 128
#define HD 256   // H*D
#define TR 72    // gemm row tile

// ---------------- scratch (device globals; no allocation allowed) -------------
__device__ __half g_feat[NN * HD];     // [N, dim*8+head] fp16 features
__device__ float g_el[NN * HH];
__device__ float g_er[NN * HH];
__device__ float g_h[NN * DD];         // layer-1 output (fp32)
__device__ float g_Wp1[F1 * HD];
__device__ float g_Wp2[DD * HD];
__device__ float g_alp1[HD], g_arp1[HD];
__device__ float g_alp2[HD], g_arp2[HD];
__device__ int   g_cnt[NN];            // INVARIANT: zero on entry to every call
__device__ int   g_rowptr[NN + 1];
__device__ int   g_fill[NN];
__device__ int   g_esrc[EE];

// ---------------- weight permutation (both layers, one small launch) ----------
__global__ void perm_kernel(const float* __restrict__ W1,
                            const float* __restrict__ al1,
                            const float* __restrict__ ar1,
                            const float* __restrict__ W2,
                            const float* __restrict__ al2,
                            const float* __restrict__ ar2) {
    int t = blockIdx.x * 256 + threadIdx.x;
    if (t < F1 * HD) {
        int k = t >> 8, j = t & 255;
        int L = ((j & 7) << 5) | (j >> 3);
        g_Wp1[t] = W1[k * HD + L];
    }
    if (t < DD * HD) {
        int k = t >> 8, j = t & 255;
        int L = ((j & 7) << 5) | (j >> 3);
        g_Wp2[t] = W2[k * HD + L];
    }
    if (t < HD) {
        int L = ((t & 7) << 5) | (t >> 3);
        g_alp1[t] = al1[L]; g_arp1[t] = ar1[L];
        g_alp2[t] = al2[L]; g_arp2[t] = ar2[L];
    }
}

// ---------------- CSR chain (runs on forked stream) ---------------------------
__global__ void hist_kernel(const int* __restrict__ dst) {
    int e = blockIdx.x * blockDim.x + threadIdx.x;
    if (e < EE) atomicAdd(&g_cnt[dst[e]], 1);
}

__global__ void scan_kernel() {   // also restores g_cnt = 0 invariant
    __shared__ int ssum[1024];
    int t = threadIdx.x;
    const int chunk = (NN + 1023) / 1024;
    int b = t * chunk, e = min(b + chunk, NN);
    int s = 0;
    for (int i = b; i < e; i++) s += g_cnt[i];
    ssum[t] = s;
    __syncthreads();
    for (int off = 1; off < 1024; off <<= 1) {
        int v = (t >= off) ? ssum[t - off] : 0;
        __syncthreads();
        ssum[t] += v;
        __syncthreads();
    }
    int pref = (t > 0) ? ssum[t - 1] : 0;
    for (int i = b; i < e; i++) {
        int c = g_cnt[i];
        g_rowptr[i] = pref;
        g_fill[i]   = pref;
        g_cnt[i]    = 0;
        pref += c;
    }
    if (t == 1023) g_rowptr[NN] = ssum[1023];
}

__global__ void scatter_kernel(const int* __restrict__ src,
                               const int* __restrict__ dst) {
    int e = blockIdx.x * blockDim.x + threadIdx.x;
    if (e < EE) {
        int p = atomicAdd(&g_fill[dst[e]], 1);
        g_esrc[p] = src[e];
    }
}

// ---------------- GEMM + fused el/er, fp16 feat output ------------------------
// 512 threads, tile 72 rows x 256 cols; thread: 4 cols x 9 rows. Full W in smem.
template <int K>
__global__ __launch_bounds__(512) void gemm_kernel(const float* __restrict__ X,
                                                   const float* __restrict__ Wp,
                                                   const float* __restrict__ alp,
                                                   const float* __restrict__ arp,
                                                   int n) {
    extern __shared__ float sh[];
    float* Wsh = sh;            // [K][256] k-major
    float* Xsh = sh + K * HD;   // [TR][K]
    int tid = threadIdx.x;

    for (int idx = tid; idx < K * HD; idx += 512)
        Wsh[idx] = Wp[idx];

    int r0 = blockIdx.x * TR;
    int nr = min(TR, n - r0);
    for (int idx = tid; idx < nr * K; idx += 512)
        Xsh[idx] = X[(size_t)r0 * K + idx];
    __syncthreads();

    int col = (tid & 63) * 4;
    int rg = (tid >> 6) * 9;

    float acc[9][4];
#pragma unroll
    for (int r = 0; r < 9; r++)
#pragma unroll
        for (int c = 0; c < 4; c++) acc[r][c] = 0.f;

#pragma unroll 4
    for (int k = 0; k < K; k += 4) {
        float4 w0 = *(const float4*)(Wsh + (k + 0) * HD + col);
        float4 w1 = *(const float4*)(Wsh + (k + 1) * HD + col);
        float4 w2 = *(const float4*)(Wsh + (k + 2) * HD + col);
        float4 w3 = *(const float4*)(Wsh + (k + 3) * HD + col);
#pragma unroll
        for (int r = 0; r < 9; r++) {
            float4 xv = *(const float4*)(Xsh + (rg + r) * K + k);
            acc[r][0] = fmaf(xv.x, w0.x, acc[r][0]);
            acc[r][1] = fmaf(xv.x, w0.y, acc[r][1]);
            acc[r][2] = fmaf(xv.x, w0.z, acc[r][2]);
            acc[r][3] = fmaf(xv.x, w0.w, acc[r][3]);
            acc[r][0] = fmaf(xv.y, w1.x, acc[r][0]);
            acc[r][1] = fmaf(xv.y, w1.y, acc[r][1]);
            acc[r][2] = fmaf(xv.y, w1.z, acc[r][2]);
            acc[r][3] = fmaf(xv.y, w1.w, acc[r][3]);
            acc[r][0] = fmaf(xv.z, w2.x, acc[r][0]);
            acc[r][1] = fmaf(xv.z, w2.y, acc[r][1]);
            acc[r][2] = fmaf(xv.z, w2.z, acc[r][2]);
            acc[r][3] = fmaf(xv.z, w2.w, acc[r][3]);
            acc[r][0] = fmaf(xv.w, w3.x, acc[r][0]);
            acc[r][1] = fmaf(xv.w, w3.y, acc[r][1]);
            acc[r][2] = fmaf(xv.w, w3.z, acc[r][2]);
            acc[r][3] = fmaf(xv.w, w3.w, acc[r][3]);
        }
    }

    // fp16 feat to global
#pragma unroll
    for (int r = 0; r < 9; r++) {
        int row = rg + r;
        if (row < nr) {
            __half2 h0 = __floats2half2_rn(acc[r][0], acc[r][1]);
            __half2 h1 = __floats2half2_rn(acc[r][2], acc[r][3]);
            uint2 u = make_uint2(*(unsigned*)&h0, *(unsigned*)&h1);
            *(uint2*)(&g_feat[(size_t)(r0 + row) * HD + col]) = u;
        }
    }

    // stage fp32 feat in smem (reuses Wsh/Xsh space), then per-warp el/er
    __syncthreads();
    float* stage = sh;          // [TR][HD]
#pragma unroll
    for (int r = 0; r < 9; r++) {
        int row = rg + r;
        if (row < nr)
            *(float4*)(stage + row * HD + col) =
                make_float4(acc[r][0], acc[r][1], acc[r][2], acc[r][3]);
    }
    __syncthreads();

    int wid = tid >> 5, lane = tid & 31;
    float av[8], bv[8];
    {
        const float4* ap = (const float4*)(alp + lane * 8);
        const float4* bp = (const float4*)(arp + lane * 8);
        float4 a0 = ap[0], a1 = ap[1], b0 = bp[0], b1 = bp[1];
        av[0]=a0.x; av[1]=a0.y; av[2]=a0.z; av[3]=a0.w;
        av[4]=a1.x; av[5]=a1.y; av[6]=a1.z; av[7]=a1.w;
        bv[0]=b0.x; bv[1]=b0.y; bv[2]=b0.z; bv[3]=b0.w;
        bv[4]=b1.x; bv[5]=b1.y; bv[6]=b1.z; bv[7]=b1.w;
    }
    for (int row = wid; row < nr; row += 16) {
        const float4* f4 = (const float4*)(stage + row * HD + lane * 8);
        float4 f0 = f4[0], f1 = f4[1];
        float pa[8] = {f0.x*av[0], f0.y*av[1], f0.z*av[2], f0.w*av[3],
                       f1.x*av[4], f1.y*av[5], f1.z*av[6], f1.w*av[7]};
        float pb[8] = {f0.x*bv[0], f0.y*bv[1], f0.z*bv[2], f0.w*bv[3],
                       f1.x*bv[4], f1.y*bv[5], f1.z*bv[6], f1.w*bv[7]};
#pragma unroll
        for (int h = 0; h < 8; h++) {
#pragma unroll
            for (int off = 16; off; off >>= 1) {
                pa[h] += __shfl_xor_sync(0xffffffffu, pa[h], off);
                pb[h] += __shfl_xor_sync(0xffffffffu, pb[h], off);
            }
        }
        if (lane == 0) {
            float* elp = g_el + (size_t)(r0 + row) * HH;
            float* erp = g_er + (size_t)(r0 + row) * HH;
            *(float4*)(elp)     = make_float4(pa[0], pa[1], pa[2], pa[3]);
            *(float4*)(elp + 4) = make_float4(pa[4], pa[5], pa[6], pa[7]);
            *(float4*)(erp)     = make_float4(pb[0], pb[1], pb[2], pb[3]);
            *(float4*)(erp + 4) = make_float4(pb[4], pb[5], pb[6], pb[7]);
        }
    }
}

// ---------------- aggregation (warp per dst node, fp16 feat) ------------------
template <bool RELU_BEFORE_MEAN>
__global__ void agg_kernel(const float* __restrict__ bias,
                           float* __restrict__ out) {
    int node = blockIdx.x * (blockDim.x >> 5) + (threadIdx.x >> 5);
    if (node >= NN) return;
    int lane = threadIdx.x & 31;
    int hh = lane & 7;
    float er_l = g_er[node * HH + hh];
    int beg = g_rowptr[node], end = g_rowptr[node + 1];

    float acc[8];
#pragma unroll
    for (int h = 0; h < 8; h++) acc[h] = 0.f;
    float den_l = 0.f;

    int i = beg;
    for (; i + 2 <= end; i += 2) {
        int s0 = g_esrc[i];
        int s1 = g_esrc[i + 1];
        float el0 = __ldg(g_el + s0 * HH + hh);
        float el1 = __ldg(g_el + s1 * HH + hh);
        uint4 u0 = *(const uint4*)(&g_feat[(size_t)s0 * HD + lane * 8]);
        uint4 u1 = *(const uint4*)(&g_feat[(size_t)s1 * HD + lane * 8]);
        float v0 = el0 + er_l; v0 = v0 > 0.f ? v0 : 0.2f * v0;
        float v1 = el1 + er_l; v1 = v1 > 0.f ? v1 : 0.2f * v1;
        float e0 = __expf(v0);
        float e1 = __expf(v1);
        den_l += e0 + e1;
        float2 fa[4] = {__half22float2(*(__half2*)&u0.x), __half22float2(*(__half2*)&u0.y),
                        __half22float2(*(__half2*)&u0.z), __half22float2(*(__half2*)&u0.w)};
        float2 fb[4] = {__half22float2(*(__half2*)&u1.x), __half22float2(*(__half2*)&u1.y),
                        __half22float2(*(__half2*)&u1.z), __half22float2(*(__half2*)&u1.w)};
#pragma unroll
        for (int h = 0; h < 8; h++) {
            float w0 = __shfl_sync(0xffffffffu, e0, h);
            float w1 = __shfl_sync(0xffffffffu, e1, h);
            float f0 = (h & 1) ? fa[h >> 1].y : fa[h >> 1].x;
            float f1 = (h & 1) ? fb[h >> 1].y : fb[h >> 1].x;
            acc[h] = fmaf(w0, f0, acc[h]);
            acc[h] = fmaf(w1, f1, acc[h]);
        }
    }
    if (i < end) {
        int s = g_esrc[i];
        float elv = __ldg(g_el + s * HH + hh);
        uint4 u0 = *(const uint4*)(&g_feat[(size_t)s * HD + lane * 8]);
        float v = elv + er_l; v = v > 0.f ? v : 0.2f * v;
        float e = __expf(v);
        den_l += e;
        float2 fa[4] = {__half22float2(*(__half2*)&u0.x), __half22float2(*(__half2*)&u0.y),
                        __half22float2(*(__half2*)&u0.z), __half22float2(*(__half2*)&u0.w)};
#pragma unroll
        for (int h = 0; h < 8; h++) {
            float w = __shfl_sync(0xffffffffu, e, h);
            float f = (h & 1) ? fa[h >> 1].y : fa[h >> 1].x;
            acc[h] = fmaf(w, f, acc[h]);
        }
    }

    float sum = 0.f;
#pragma unroll
    for (int h = 0; h < 8; h++) {
        float dh = __shfl_sync(0xffffffffu, den_l, h);
        float r = (dh > 0.f) ? acc[h] / dh : 0.f;
        r += bias[h * DD + lane];
        if (RELU_BEFORE_MEAN) r = fmaxf(r, 0.f);
        sum += r;
    }
    out[node * DD + lane] = sum * 0.125f;
}

// ---------------- stream/event resources (created once, pre-capture) ----------
struct HxRes {
    cudaStream_t s2;
    cudaEvent_t e0, e1;
    HxRes() {
        cudaStreamCreateWithFlags(&s2, cudaStreamNonBlocking);
        cudaEventCreateWithFlags(&e0, cudaEventDisableTiming);
        cudaEventCreateWithFlags(&e1, cudaEventDisableTiming);
    }
};
static HxRes& hx() { static HxRes r; return r; }

// ---------------- launcher -----------------------------------------------------
extern "C" void kernel_launch(void* const* d_in, const int* in_sizes, int n_in,
                              void* d_out, int out_size) {
    const float* x   = (const float*)d_in[0];
    const int*   src = (const int*)d_in[1];
    const int*   dst = (const int*)d_in[2];
    const float* W1  = (const float*)d_in[3];
    const float* al1 = (const float*)d_in[4];
    const float* ar1 = (const float*)d_in[5];
    const float* b1  = (const float*)d_in[6];
    const float* W2  = (const float*)d_in[7];
    const float* al2 = (const float*)d_in[8];
    const float* ar2 = (const float*)d_in[9];
    const float* b2  = (const float*)d_in[10];
    float* out = (float*)d_out;

    float *hbuf, *Wp1, *Wp2, *alp1, *arp1, *alp2, *arp2;
    cudaGetSymbolAddress((void**)&hbuf, g_h);
    cudaGetSymbolAddress((void**)&Wp1, g_Wp1);
    cudaGetSymbolAddress((void**)&Wp2, g_Wp2);
    cudaGetSymbolAddress((void**)&alp1, g_alp1);
    cudaGetSymbolAddress((void**)&arp1, g_arp1);
    cudaGetSymbolAddress((void**)&alp2, g_alp2);
    cudaGetSymbolAddress((void**)&arp2, g_arp2);

    const int NT = (NN + TR - 1) / TR;  // 278 tiles
    constexpr int smem1 = (F1 * HD + TR * F1) * sizeof(float);  // 167936
    constexpr int smem2 = TR * HD * sizeof(float);              // 73728 (covers W+X+stage)
    cudaFuncSetAttribute(gemm_kernel<F1>,
                         cudaFuncAttributeMaxDynamicSharedMemorySize, smem1);
    cudaFuncSetAttribute(gemm_kernel<DD>,
                         cudaFuncAttributeMaxDynamicSharedMemorySize, smem2);

    HxRes& R = hx();

    // fork: CSR chain on s2, overlapped with perm + gemm1
    cudaEventRecord(R.e0, 0);
    cudaStreamWaitEvent(R.s2, R.e0, 0);
    hist_kernel<<<(EE + 255) / 256, 256, 0, R.s2>>>(dst);
    scan_kernel<<<1, 1024, 0, R.s2>>>();
    scatter_kernel<<<(EE + 255) / 256, 256, 0, R.s2>>>(src, dst);
    cudaEventRecord(R.e1, R.s2);

    // main stream: layer-1 GEMM (+fused el/er, fp16 feat)
    perm_kernel<<<(F1 * HD + 255) / 256, 256>>>(W1, al1, ar1, W2, al2, ar2);
    gemm_kernel<F1><<<NT, 512, smem1>>>(x, Wp1, alp1, arp1, NN);

    // join, then aggregate layer 1
    cudaStreamWaitEvent(0, R.e1, 0);
    agg_kernel<true><<<(NN + 7) / 8, 256>>>(b1, hbuf);

    // layer 2
    gemm_kernel<DD><<<NT, 512, smem2>>>(hbuf, Wp2, alp2, arp2, NN);
    agg_kernel<false><<<(NN + 7) / 8, 256>>>(b2, out);
}

// round 6
// speedup vs baseline: 1.5310x; 1.1607x over previous
#include <cuda_runtime.h>
#include <cuda_fp16.h>
#include <cuda_bf16.h>

#define NN 20000
#define EE 320000
#define HH 8
#define DD 32
#define F1 128
#define HD 256   // H*D
#define TRB 64   // tensor-core gemm row tile

// ---------------- scratch (device globals; no allocation allowed) -------------
__device__ __half g_feat[NN * HD];     // [N, dim*8+head] fp16 features
__device__ float g_el[NN * HH];
__device__ float g_er[NN * HH];
__device__ float g_h[NN * DD];         // layer-1 output (fp32)
__device__ float g_Wp1[F1 * HD];       // tf32-rounded bits, permuted cols
__device__ float g_Wp2[DD * HD];
__device__ float g_alp1[HD], g_arp1[HD];
__device__ float g_alp2[HD], g_arp2[HD];
__device__ int   g_cnt[NN];            // INVARIANT: zero on entry to every call
__device__ int   g_rowptr[NN + 1];
__device__ int   g_fill[NN];
__device__ int   g_esrc[EE];

__device__ __forceinline__ unsigned f2tf32(float f) {
    unsigned u;
    asm("cvt.rna.tf32.f32 %0, %1;" : "=r"(u) : "f"(f));
    return u;
}

__device__ __forceinline__ void mma_tf32(float& d0, float& d1, float& d2, float& d3,
                                         unsigned a0, unsigned a1, unsigned a2, unsigned a3,
                                         unsigned b0, unsigned b1) {
    asm volatile("mma.sync.aligned.m16n8k8.row.col.f32.tf32.tf32.f32 "
                 "{%0,%1,%2,%3}, {%4,%5,%6,%7}, {%8,%9}, {%0,%1,%2,%3};"
                 : "+f"(d0), "+f"(d1), "+f"(d2), "+f"(d3)
                 : "r"(a0), "r"(a1), "r"(a2), "r"(a3), "r"(b0), "r"(b1));
}

// ---------------- weight permutation + tf32 conversion ------------------------
__global__ void perm_kernel(const float* __restrict__ W1,
                            const float* __restrict__ al1,
                            const float* __restrict__ ar1,
                            const float* __restrict__ W2,
                            const float* __restrict__ al2,
                            const float* __restrict__ ar2) {
    int t = blockIdx.x * 256 + threadIdx.x;
    if (t < F1 * HD) {
        int k = t >> 8, j = t & 255;
        int L = ((j & 7) << 5) | (j >> 3);
        g_Wp1[t] = __uint_as_float(f2tf32(W1[k * HD + L]));
    }
    if (t < DD * HD) {
        int k = t >> 8, j = t & 255;
        int L = ((j & 7) << 5) | (j >> 3);
        g_Wp2[t] = __uint_as_float(f2tf32(W2[k * HD + L]));
    }
    if (t < HD) {
        int L = ((t & 7) << 5) | (t >> 3);
        g_alp1[t] = al1[L]; g_arp1[t] = ar1[L];
        g_alp2[t] = al2[L]; g_arp2[t] = ar2[L];
    }
}

// ---------------- CSR chain (runs on forked stream) ---------------------------
__global__ void hist_kernel(const int* __restrict__ dst) {
    int e = blockIdx.x * blockDim.x + threadIdx.x;
    if (e < EE) atomicAdd(&g_cnt[dst[e]], 1);
}

__global__ void scan_kernel() {   // also restores g_cnt = 0 invariant
    __shared__ int ssum[1024];
    int t = threadIdx.x;
    const int chunk = (NN + 1023) / 1024;
    int b = t * chunk, e = min(b + chunk, NN);
    int s = 0;
    for (int i = b; i < e; i++) s += g_cnt[i];
    ssum[t] = s;
    __syncthreads();
    for (int off = 1; off < 1024; off <<= 1) {
        int v = (t >= off) ? ssum[t - off] : 0;
        __syncthreads();
        ssum[t] += v;
        __syncthreads();
    }
    int pref = (t > 0) ? ssum[t - 1] : 0;
    for (int i = b; i < e; i++) {
        int c = g_cnt[i];
        g_rowptr[i] = pref;
        g_fill[i]   = pref;
        g_cnt[i]    = 0;
        pref += c;
    }
    if (t == 1023) g_rowptr[NN] = ssum[1023];
}

__global__ void scatter_kernel(const int* __restrict__ src,
                               const int* __restrict__ dst) {
    int e = blockIdx.x * blockDim.x + threadIdx.x;
    if (e < EE) {
        int p = atomicAdd(&g_fill[dst[e]], 1);
        g_esrc[p] = src[e];
    }
}

// ---------------- tensor-core GEMM + fused el/er + fp16 feat ------------------
// 256 threads = 8 warps (2 Mgroups x 4 Ngroups). Tile 64 rows x 256 cols.
// Warp: 32 rows (2 m-tiles) x 64 cols (8 n-tiles), mma.m16n8k8 tf32.
template <int K>
__global__ __launch_bounds__(256, 2) void gemm_tc_kernel(const float* __restrict__ X,
                                                         const float* __restrict__ Wp,
                                                         const float* __restrict__ alp,
                                                         const float* __restrict__ arp,
                                                         int n) {
    constexpr int KC = (K > 64) ? 64 : K;   // W chunk rows
    constexpr int XP = K + 4;               // X row pad (bank-shift 4)
    constexpr int WP = 264;                 // W row pad (bank-shift 8)
    constexpr int STP = 260;                // stage row pad
    extern __shared__ float sh[];
    unsigned* Wsh = (unsigned*)sh;                  // [KC][WP]
    unsigned* Xsh = (unsigned*)(sh + KC * WP);      // [TRB][XP]
    int tid = threadIdx.x;
    int wid = tid >> 5, lane = tid & 31;
    int g = lane >> 2, tg = lane & 3;
    int warpM = wid >> 2, warpN = wid & 3;
    int nbase = warpN * 64;

    int r0 = blockIdx.x * TRB;
    int nr = min(TRB, n - r0);

    // X tile -> smem as tf32 bits (zero pad tail rows)
    for (int idx = tid; idx < TRB * K; idx += 256) {
        int r = idx / K, c = idx % K;
        float v = (r < nr) ? X[(size_t)(r0 + r) * K + c] : 0.f;
        Xsh[r * XP + c] = f2tf32(v);
    }

    float acc[2][8][4];
#pragma unroll
    for (int m = 0; m < 2; m++)
#pragma unroll
        for (int t = 0; t < 8; t++)
#pragma unroll
            for (int c = 0; c < 4; c++) acc[m][t][c] = 0.f;

    const unsigned* WpU = (const unsigned*)Wp;
    for (int kc = 0; kc < K; kc += KC) {
        __syncthreads();
        for (int idx = tid; idx < KC * HD; idx += 256) {
            int kk = idx >> 8, j = idx & 255;
            Wsh[kk * WP + j] = WpU[(kc + kk) * HD + j];
        }
        __syncthreads();

#pragma unroll
        for (int kk = 0; kk < KC; kk += 8) {
            int k0 = kc + kk;
            unsigned a[2][4];
#pragma unroll
            for (int m = 0; m < 2; m++) {
                int rb = warpM * 32 + m * 16;
                a[m][0] = Xsh[(rb + g) * XP + k0 + tg];
                a[m][1] = Xsh[(rb + g + 8) * XP + k0 + tg];
                a[m][2] = Xsh[(rb + g) * XP + k0 + tg + 4];
                a[m][3] = Xsh[(rb + g + 8) * XP + k0 + tg + 4];
            }
#pragma unroll
            for (int t = 0; t < 8; t++) {
                int ncol = nbase + t * 8 + g;
                unsigned b0 = Wsh[(kk + tg) * WP + ncol];
                unsigned b1 = Wsh[(kk + tg + 4) * WP + ncol];
                mma_tf32(acc[0][t][0], acc[0][t][1], acc[0][t][2], acc[0][t][3],
                         a[0][0], a[0][1], a[0][2], a[0][3], b0, b1);
                mma_tf32(acc[1][t][0], acc[1][t][1], acc[1][t][2], acc[1][t][3],
                         a[1][0], a[1][1], a[1][2], a[1][3], b0, b1);
            }
        }
    }

    // stage fp32 result to smem (reuse W/X space)
    __syncthreads();
    float* stage = sh;          // [TRB][STP]
#pragma unroll
    for (int m = 0; m < 2; m++) {
        int rb = warpM * 32 + m * 16;
#pragma unroll
        for (int t = 0; t < 8; t++) {
            int c = nbase + t * 8 + 2 * tg;
            *(float2*)&stage[(rb + g) * STP + c] =
                make_float2(acc[m][t][0], acc[m][t][1]);
            *(float2*)&stage[(rb + g + 8) * STP + c] =
                make_float2(acc[m][t][2], acc[m][t][3]);
        }
    }
    __syncthreads();

    // fp16 feat writeout (coalesced)
    for (int i = tid; i < nr * 32; i += 256) {
        int row = i >> 5, cg = i & 31;
        const float4* s4 = (const float4*)&stage[row * STP + cg * 8];
        float4 f0 = s4[0], f1 = s4[1];
        __half2 h0 = __floats2half2_rn(f0.x, f0.y);
        __half2 h1 = __floats2half2_rn(f0.z, f0.w);
        __half2 h2 = __floats2half2_rn(f1.x, f1.y);
        __half2 h3 = __floats2half2_rn(f1.z, f1.w);
        uint4 u = make_uint4(*(unsigned*)&h0, *(unsigned*)&h1,
                             *(unsigned*)&h2, *(unsigned*)&h3);
        *(uint4*)(&g_feat[(size_t)(r0 + row) * HD + cg * 8]) = u;
    }

    // el/er: warp per row
    float av[8], bv[8];
    {
        const float4* ap = (const float4*)(alp + lane * 8);
        const float4* bp = (const float4*)(arp + lane * 8);
        float4 a0 = ap[0], a1 = ap[1], b0 = bp[0], b1 = bp[1];
        av[0]=a0.x; av[1]=a0.y; av[2]=a0.z; av[3]=a0.w;
        av[4]=a1.x; av[5]=a1.y; av[6]=a1.z; av[7]=a1.w;
        bv[0]=b0.x; bv[1]=b0.y; bv[2]=b0.z; bv[3]=b0.w;
        bv[4]=b1.x; bv[5]=b1.y; bv[6]=b1.z; bv[7]=b1.w;
    }
    for (int row = wid; row < nr; row += 8) {
        const float4* f4 = (const float4*)(stage + row * STP + lane * 8);
        float4 f0 = f4[0], f1 = f4[1];
        float pa[8] = {f0.x*av[0], f0.y*av[1], f0.z*av[2], f0.w*av[3],
                       f1.x*av[4], f1.y*av[5], f1.z*av[6], f1.w*av[7]};
        float pb[8] = {f0.x*bv[0], f0.y*bv[1], f0.z*bv[2], f0.w*bv[3],
                       f1.x*bv[4], f1.y*bv[5], f1.z*bv[6], f1.w*bv[7]};
#pragma unroll
        for (int h = 0; h < 8; h++) {
#pragma unroll
            for (int off = 16; off; off >>= 1) {
                pa[h] += __shfl_xor_sync(0xffffffffu, pa[h], off);
                pb[h] += __shfl_xor_sync(0xffffffffu, pb[h], off);
            }
        }
        if (lane == 0) {
            float* elp = g_el + (size_t)(r0 + row) * HH;
            float* erp = g_er + (size_t)(r0 + row) * HH;
            *(float4*)(elp)     = make_float4(pa[0], pa[1], pa[2], pa[3]);
            *(float4*)(elp + 4) = make_float4(pa[4], pa[5], pa[6], pa[7]);
            *(float4*)(erp)     = make_float4(pb[0], pb[1], pb[2], pb[3]);
            *(float4*)(erp + 4) = make_float4(pb[4], pb[5], pb[6], pb[7]);
        }
    }
}

// ---------------- aggregation (warp per dst node, fp16 feat) ------------------
template <bool RELU_BEFORE_MEAN>
__global__ void agg_kernel(const float* __restrict__ bias,
                           float* __restrict__ out) {
    int node = blockIdx.x * (blockDim.x >> 5) + (threadIdx.x >> 5);
    if (node >= NN) return;
    int lane = threadIdx.x & 31;
    int hh = lane & 7;
    float er_l = g_er[node * HH + hh];
    int beg = g_rowptr[node], end = g_rowptr[node + 1];

    float acc[8];
#pragma unroll
    for (int h = 0; h < 8; h++) acc[h] = 0.f;
    float den_l = 0.f;

    int i = beg;
    for (; i + 2 <= end; i += 2) {
        int s0 = g_esrc[i];
        int s1 = g_esrc[i + 1];
        float el0 = __ldg(g_el + s0 * HH + hh);
        float el1 = __ldg(g_el + s1 * HH + hh);
        uint4 u0 = *(const uint4*)(&g_feat[(size_t)s0 * HD + lane * 8]);
        uint4 u1 = *(const uint4*)(&g_feat[(size_t)s1 * HD + lane * 8]);
        float v0 = el0 + er_l; v0 = v0 > 0.f ? v0 : 0.2f * v0;
        float v1 = el1 + er_l; v1 = v1 > 0.f ? v1 : 0.2f * v1;
        float e0 = __expf(v0);
        float e1 = __expf(v1);
        den_l += e0 + e1;
        float2 fa[4] = {__half22float2(*(__half2*)&u0.x), __half22float2(*(__half2*)&u0.y),
                        __half22float2(*(__half2*)&u0.z), __half22float2(*(__half2*)&u0.w)};
        float2 fb[4] = {__half22float2(*(__half2*)&u1.x), __half22float2(*(__half2*)&u1.y),
                        __half22float2(*(__half2*)&u1.z), __half22float2(*(__half2*)&u1.w)};
#pragma unroll
        for (int h = 0; h < 8; h++) {
            float w0 = __shfl_sync(0xffffffffu, e0, h);
            float w1 = __shfl_sync(0xffffffffu, e1, h);
            float f0 = (h & 1) ? fa[h >> 1].y : fa[h >> 1].x;
            float f1 = (h & 1) ? fb[h >> 1].y : fb[h >> 1].x;
            acc[h] = fmaf(w0, f0, acc[h]);
            acc[h] = fmaf(w1, f1, acc[h]);
        }
    }
    if (i < end) {
        int s = g_esrc[i];
        float elv = __ldg(g_el + s * HH + hh);
        uint4 u0 = *(const uint4*)(&g_feat[(size_t)s * HD + lane * 8]);
        float v = elv + er_l; v = v > 0.f ? v : 0.2f * v;
        float e = __expf(v);
        den_l += e;
        float2 fa[4] = {__half22float2(*(__half2*)&u0.x), __half22float2(*(__half2*)&u0.y),
                        __half22float2(*(__half2*)&u0.z), __half22float2(*(__half2*)&u0.w)};
#pragma unroll
        for (int h = 0; h < 8; h++) {
            float w = __shfl_sync(0xffffffffu, e, h);
            float f = (h & 1) ? fa[h >> 1].y : fa[h >> 1].x;
            acc[h] = fmaf(w, f, acc[h]);
        }
    }

    float sum = 0.f;
#pragma unroll
    for (int h = 0; h < 8; h++) {
        float dh = __shfl_sync(0xffffffffu, den_l, h);
        float r = (dh > 0.f) ? acc[h] / dh : 0.f;
        r += bias[h * DD + lane];
        if (RELU_BEFORE_MEAN) r = fmaxf(r, 0.f);
        sum += r;
    }
    out[node * DD + lane] = sum * 0.125f;
}

// ---------------- stream/event resources (created once, pre-capture) ----------
struct HxRes {
    cudaStream_t s2;
    cudaEvent_t e0, e1;
    HxRes() {
        cudaStreamCreateWithFlags(&s2, cudaStreamNonBlocking);
        cudaEventCreateWithFlags(&e0, cudaEventDisableTiming);
        cudaEventCreateWithFlags(&e1, cudaEventDisableTiming);
    }
};
static HxRes& hx() { static HxRes r; return r; }

// ---------------- launcher -----------------------------------------------------
extern "C" void kernel_launch(void* const* d_in, const int* in_sizes, int n_in,
                              void* d_out, int out_size) {
    const float* x   = (const float*)d_in[0];
    const int*   src = (const int*)d_in[1];
    const int*   dst = (const int*)d_in[2];
    const float* W1  = (const float*)d_in[3];
    const float* al1 = (const float*)d_in[4];
    const float* ar1 = (const float*)d_in[5];
    const float* b1  = (const float*)d_in[6];
    const float* W2  = (const float*)d_in[7];
    const float* al2 = (const float*)d_in[8];
    const float* ar2 = (const float*)d_in[9];
    const float* b2  = (const float*)d_in[10];
    float* out = (float*)d_out;

    float *hbuf, *Wp1, *Wp2, *alp1, *arp1, *alp2, *arp2;
    cudaGetSymbolAddress((void**)&hbuf, g_h);
    cudaGetSymbolAddress((void**)&Wp1, g_Wp1);
    cudaGetSymbolAddress((void**)&Wp2, g_Wp2);
    cudaGetSymbolAddress((void**)&alp1, g_alp1);
    cudaGetSymbolAddress((void**)&arp1, g_arp1);
    cudaGetSymbolAddress((void**)&alp2, g_alp2);
    cudaGetSymbolAddress((void**)&arp2, g_arp2);

    const int NTB = (NN + TRB - 1) / TRB;  // 313 tiles
    // smem: gemm1 = max(64*264 + 64*132, 64*260)*4 = 101376 B
    //       gemm2 = max(32*264 + 64*36,  64*260)*4 = 66560 B
    constexpr int smem1 = (64 * 264 + 64 * 132) * sizeof(float);
    constexpr int smem2 = (64 * 260) * sizeof(float);
    cudaFuncSetAttribute(gemm_tc_kernel<F1>,
                         cudaFuncAttributeMaxDynamicSharedMemorySize, smem1);
    cudaFuncSetAttribute(gemm_tc_kernel<DD>,
                         cudaFuncAttributeMaxDynamicSharedMemorySize, smem2);

    HxRes& R = hx();

    // fork: CSR chain on s2, overlapped with perm + gemm1
    cudaEventRecord(R.e0, 0);
    cudaStreamWaitEvent(R.s2, R.e0, 0);
    hist_kernel<<<(EE + 255) / 256, 256, 0, R.s2>>>(dst);
    scan_kernel<<<1, 1024, 0, R.s2>>>();
    scatter_kernel<<<(EE + 255) / 256, 256, 0, R.s2>>>(src, dst);
    cudaEventRecord(R.e1, R.s2);

    // main stream: layer-1 GEMM (+fused el/er, fp16 feat)
    perm_kernel<<<(F1 * HD + 255) / 256, 256>>>(W1, al1, ar1, W2, al2, ar2);
    gemm_tc_kernel<F1><<<NTB, 256, smem1>>>(x, Wp1, alp1, arp1, NN);

    // join, then aggregate layer 1
    cudaStreamWaitEvent(0, R.e1, 0);
    agg_kernel<true><<<(NN + 7) / 8, 256>>>(b1, hbuf);

    // layer 2
    gemm_tc_kernel<DD><<<NTB, 256, smem2>>>(hbuf, Wp2, alp2, arp2, NN);
    agg_kernel<false><<<(NN + 7) / 8, 256>>>(b2, out);
}